// round 16
// baseline (speedup 1.0000x reference)
#include <cuda_runtime.h>
#include <cuda_fp16.h>
#include <cstdint>

#define N_NODES 128
#define V_PTS   2048
#define XYZ     63
#define NG      9          // node groups: 8 groups of 15 + 1 group of 8

// ---- output layout ----
#define OFF_C      0
#define OFF_D      6144
#define OFF_EI     8192
#define OFF_DELTA  12288
#define OFF_MEAN   12672
#define OFF_LOGVAR 13696

// ---- scratch ----
__device__ float g_ei[N_NODES * 32];
__device__ float g_b1eff[N_NODES * 64];
__device__ float g_e[N_NODES * V_PTS];
__device__ float g_fpart[NG * V_PTS * 256];
// per-node packed weight image: f16, row stride 72 halves (4032 float4 per node)
__device__ float4 g_Wpad4[N_NODES * 4032];

// ---- field smem layout (BYTE offsets) ----
#define FB_BUFA  0                         // 128 x 72 f16 = 18432
#define FB_BUFB  18432
#define FB_LCRAW 36864                     // 8068 fp32 words = 32272 B
#define FB_W(b)  (69136 + (b) * 64512)    // f16 weight image, double-buffered
#define FB_BS(b) (198160 + (b) * 2304)    // B1@0 B2@256 B3@512 B4@768 E@1792 (bytes)
#define FB_TOT   202768

// pair-scoped named barrier: the two warps sharing mb (64 threads)
#define PAIRB(mbid) asm volatile("bar.sync %0, 64;" :: "r"((mbid) + 1) : "memory")

__device__ __forceinline__ uint32_t s2u(const void* p) {
    return (uint32_t)__cvta_generic_to_shared(p);
}
#define CP16(d, s) asm volatile("cp.async.ca.shared.global [%0], [%1], 16;" :: "r"(d), "l"(s))
#define CP_COMMIT() asm volatile("cp.async.commit_group;")
#define CP_WAIT0()  asm volatile("cp.async.wait_group 0;" ::: "memory")

__device__ __forceinline__ void mma_f16(float c[4], uint32_t a0, uint32_t a1,
                                        uint32_t a2, uint32_t a3,
                                        uint32_t b0, uint32_t b1) {
    asm volatile(
        "mma.sync.aligned.m16n8k16.row.col.f32.f16.f16.f32 "
        "{%0,%1,%2,%3}, {%4,%5,%6,%7}, {%8,%9}, {%0,%1,%2,%3};"
        : "+f"(c[0]), "+f"(c[1]), "+f"(c[2]), "+f"(c[3])
        : "r"(a0), "r"(a1), "r"(a2), "r"(a3), "r"(b0), "r"(b1));
}

// one warp computes a 16x32 tile of C[128 x N] = A[128 x 64] * W[N x 64]^T, f16
// word layout: rows of 36 u32 (72 f16). Reads ONLY rows mb*16..mb*16+15.
__device__ __forceinline__ void gemm16x32_f16(const uint32_t* __restrict__ Ain,
                                              const uint32_t* __restrict__ Ws,
                                              int mb, int cb, int lane,
                                              float c[4][4]) {
    int r = mb * 16 + (lane >> 2);
    int q = lane & 3;
    const uint32_t* ar0 = Ain + r * 36 + q;
    const uint32_t* ar1 = ar0 + 8 * 36;
    const uint32_t* bc  = Ws + (cb + (lane >> 2)) * 36 + q;
    #pragma unroll
    for (int ks = 0; ks < 4; ks++) {
        uint32_t a0 = ar0[ks * 8];
        uint32_t a1 = ar1[ks * 8];
        uint32_t a2 = ar0[ks * 8 + 4];
        uint32_t a3 = ar1[ks * 8 + 4];
        #pragma unroll
        for (int n8 = 0; n8 < 4; n8++) {
            uint32_t b0 = bc[n8 * 8 * 36 + ks * 8];
            uint32_t b1 = bc[n8 * 8 * 36 + ks * 8 + 4];
            mma_f16(c[n8], a0, a1, a2, a3, b0, b1);
        }
    }
}

// async prefetch of one node's weights/biases/E + raw lc tile
__device__ __forceinline__ void prefetch_node(char* smc, int buf, int n, int v0, int tid,
    const float* __restrict__ bf2, const float* __restrict__ bf3,
    const float* __restrict__ bf4, const float* __restrict__ lc)
{
    uint32_t wdst = s2u(smc + FB_W(buf));
    const float4* wsrc = &g_Wpad4[(size_t)n * 4032];
    #pragma unroll 2
    for (int i = tid; i < 4032; i += 512)
        CP16(wdst + i * 16, wsrc + i);

    uint32_t bdst = s2u(smc + FB_BS(buf));
    if (tid < 144) {
        const float4* src;
        uint32_t d;
        if (tid < 16)       { src = (const float4*)(g_b1eff + n * 64) + tid;                     d = bdst + tid * 16; }
        else if (tid < 32)  { src = (const float4*)(bf2 + n * 64) + (tid - 16);                  d = bdst + 256 + (tid - 16) * 16; }
        else if (tid < 48)  { src = (const float4*)(bf3 + n * 64) + (tid - 32);                  d = bdst + 512 + (tid - 32) * 16; }
        else if (tid < 112) { src = (const float4*)(bf4 + n * 256) + (tid - 48);                 d = bdst + 768 + (tid - 48) * 16; }
        else                { src = (const float4*)(g_e + (size_t)n * V_PTS + v0) + (tid - 112); d = bdst + 1792 + (tid - 112) * 16; }
        CP16(d, src);
    }

    const float* base = lc + ((size_t)n * V_PTS + v0) * XYZ;   // contiguous 32256 B tile
    uintptr_t ba = (uintptr_t)base & ~(uintptr_t)15;
    int off = (int)(((uintptr_t)base >> 2) & 3);
    int nch = 2016 + (off ? 1 : 0);
    uint32_t ldst = s2u(smc + FB_LCRAW);
    for (int i = tid; i < nch; i += 512)
        CP16(ldst + i * 16, (const void*)(ba + (uintptr_t)i * 16));
}

// =====================================================================
// Kernel A: encoder + decoder + effective L1 bias (fp32 exact)
// =====================================================================
__global__ void setup_kernel(
    const float* __restrict__ poses, const float* __restrict__ t_ped,
    const float* __restrict__ w,
    const float* __restrict__ Wec1, const float* __restrict__ bec1,
    const float* __restrict__ Wec21, const float* __restrict__ bec21,
    const float* __restrict__ Wec22, const float* __restrict__ bec22,
    const float* __restrict__ Wdc1, const float* __restrict__ bdc1,
    const float* __restrict__ Wdc21, const float* __restrict__ bdc21,
    const float* __restrict__ Wdc22, const float* __restrict__ bdc22,
    const float* __restrict__ Wf1, const float* __restrict__ bf1,
    float* __restrict__ out)
{
    int n = blockIdx.x;
    int t = threadIdx.x;
    __shared__ float s_in[88], s_net[64], s_mean[8], s_din[80], s_net2[64], s_ei[32];

    if (t < 72)       s_in[t] = w[n * 24 + t / 3] * poses[n * 72 + t];
    else if (t < 88)  s_in[t] = t_ped[t - 72];
    __syncthreads();

    if (t < 64) {
        float a = bec1[n * 64 + t];
        const float* Wr = &Wec1[(n * 64 + t) * 88];
        #pragma unroll 8
        for (int c = 0; c < 88; c++) a += Wr[c] * s_in[c];
        s_net[t] = fmaxf(a, 0.f);
    }
    __syncthreads();

    if (t < 8) {
        float m = bec21[n * 8 + t], lv = bec22[n * 8 + t];
        const float* Wm = &Wec21[(n * 8 + t) * 64];
        const float* Wl = &Wec22[(n * 8 + t) * 64];
        #pragma unroll 8
        for (int c = 0; c < 64; c++) { m += Wm[c] * s_net[c]; lv += Wl[c] * s_net[c]; }
        s_mean[t] = m;
        out[OFF_MEAN + n * 8 + t] = m;
        out[OFF_LOGVAR + n * 8 + t] = lv;
    }
    __syncthreads();

    if (t < 72)      s_din[t] = s_in[t];
    else if (t < 80) s_din[t] = s_mean[t - 72];
    __syncthreads();

    if (t < 64) {
        float a = bdc1[n * 64 + t];
        const float* Wr = &Wdc1[(n * 64 + t) * 80];
        #pragma unroll 8
        for (int c = 0; c < 80; c++) a += Wr[c] * s_din[c];
        s_net2[t] = fmaxf(a, 0.f);
    }
    __syncthreads();

    if (t < 32) {
        float a = bdc21[n * 32 + t];
        const float* Wr = &Wdc21[(n * 32 + t) * 64];
        #pragma unroll 8
        for (int c = 0; c < 64; c++) a += Wr[c] * s_net2[c];
        s_ei[t] = a;
        g_ei[n * 32 + t] = a;
        out[OFF_EI + n * 32 + t] = a;
    }
    if (t >= 32 && t < 35) {
        int j = t - 32;
        float a = bdc22[n * 3 + j];
        const float* Wr = &Wdc22[(n * 3 + j) * 64];
        #pragma unroll 8
        for (int c = 0; c < 64; c++) a += Wr[c] * s_net2[c];
        out[OFF_DELTA + n * 3 + j] = a;
    }
    __syncthreads();

    if (t < 64) {
        float a = bf1[n * 64 + t];
        const float* Wr = &Wf1[(size_t)(n * 64 + t) * 95];
        #pragma unroll 8
        for (int c = 0; c < 32; c++) a += Wr[c] * s_ei[c];
        g_b1eff[n * 64 + t] = a;
    }
}

// =====================================================================
// Kernel E+B merged: blocks 0..127 prepack weights -> f16 images,
//                    blocks 128..135 compute RBF blend weights.
// =====================================================================
__global__ void prep_kernel(const float* __restrict__ Wf1,
                            const float* __restrict__ Wf2,
                            const float* __restrict__ Wf3,
                            const float* __restrict__ Wf4,
                            const float* __restrict__ wpts,
                            const float* __restrict__ nodes_posed)
{
    int bid = blockIdx.x, tid = threadIdx.x;
    if (bid < N_NODES) {
        int n = bid;
        __half* dst = (__half*)&g_Wpad4[(size_t)n * 4032];

        for (int i = tid; i < 4608; i += 256) {            // W1 [64 x 72]
            int j = i / 72, k = i - j * 72;
            float v = (k < XYZ) ? Wf1[(size_t)(n * 64 + j) * 95 + 32 + k] : 0.f;
            dst[i] = __float2half_rn(v);
        }
        for (int i = tid; i < 4608; i += 256) {            // W2
            int j = i / 72, k = i - j * 72;
            float v = (k < 64) ? Wf2[(size_t)n * 4096 + j * 64 + k] : 0.f;
            dst[4608 + i] = __float2half_rn(v);
        }
        for (int i = tid; i < 4608; i += 256) {            // W3
            int j = i / 72, k = i - j * 72;
            float v = (k < 64) ? Wf3[(size_t)n * 4096 + j * 64 + k] : 0.f;
            dst[9216 + i] = __float2half_rn(v);
        }
        for (int i = tid; i < 18432; i += 256) {           // W4 [256 x 72]
            int j = i / 72, k = i - j * 72;
            float v = (k < 64) ? Wf4[(size_t)n * 16384 + j * 64 + k] : 0.f;
            dst[13824 + i] = __float2half_rn(v);
        }
    } else {
        int v = (bid - N_NODES) * 256 + tid;
        if (v >= V_PTS) return;
        float px = wpts[v * 3 + 0], py = wpts[v * 3 + 1], pz = wpts[v * 3 + 2];
        float denom = 0.f;
        for (int n = 0; n < N_NODES; n++) {
            float dx = px - nodes_posed[n * 3 + 0];
            float dy = py - nodes_posed[n * 3 + 1];
            float dz = pz - nodes_posed[n * 3 + 2];
            float d2 = dx * dx + dy * dy + dz * dz;
            float influ = expf(-d2 * (1.0f / 0.18f)) - 0.01f;
            float e = (influ >= 0.f) ? (influ + 1e-7f) : 0.f;
            denom += fmaxf(influ, 0.f) + 1e-7f;
            g_e[n * V_PTS + v] = e;
        }
        float inv = 1.0f / denom;
        for (int n = 0; n < N_NODES; n++) g_e[n * V_PTS + v] *= inv;
    }
}

// =====================================================================
// Kernel C: feature field via mma.sync f16 + cp.async double-buffering
// grid = (16 v-tiles) x (9 node-groups), 512 threads (16 warps)
// Inter-layer sync is PAIR-scoped (named barrier per mb, 64 threads):
// each layer's reads/writes stay within the pair's 16-row block.
// =====================================================================
__global__ void __launch_bounds__(512, 1) field_kernel(
    const float* __restrict__ local_coords,
    const float* __restrict__ bf2, const float* __restrict__ bf3,
    const float* __restrict__ bf4)
{
    extern __shared__ char smc[];
    __half*   smh = (__half*)smc;
    uint32_t* smw = (uint32_t*)smc;
    float*    smf = (float*)smc;

    int tid  = threadIdx.x;
    int wid  = tid >> 5, lane = tid & 31;
    int mb   = wid & 7;
    int nhi  = wid >> 3;
    int v0 = blockIdx.x * 128;
    int g  = blockIdx.y;
    int n0 = g * 15;
    int ncnt = (g == 8) ? 8 : 15;
    int cb = nhi * 32;

    float acc[64];
    #pragma unroll
    for (int i = 0; i < 64; i++) acc[i] = 0.f;

    int r0 = mb * 16 + (lane >> 2);
    int q2 = (lane & 3) * 2;

    // prologue: prefetch first node
    prefetch_node(smc, 0, n0, v0, tid, bf2, bf3, bf4, local_coords);
    CP_COMMIT();
    int cur = 0;

    for (int ni = 0; ni < ncnt; ni++) {
        int n = n0 + ni;
        CP_WAIT0();
        __syncthreads();   // weights[cur]/biases/lcraw complete; ALL pairs past L4 of prev node

        // ---- convert lcraw (fp32) -> BUFA (f16) ----
        {
            const float* base = local_coords + ((size_t)n * V_PTS + v0) * XYZ;
            int off = (int)(((uintptr_t)base >> 2) & 3);
            const float* lcr = (const float*)(smc + FB_LCRAW);
            #pragma unroll 4
            for (int i = tid; i < 8192; i += 512) {
                int v = i >> 6, k = i & 63;
                float val = (k < XYZ) ? lcr[off + v * 63 + k] : 0.f;
                smh[FB_BUFA / 2 + v * 72 + k] = __float2half_rn(val);
            }
        }
        __syncthreads();   // BUFA ready; lcraw free for next prefetch

        // ---- kick prefetch of next node into the other buffer ----
        if (ni + 1 < ncnt)
            prefetch_node(smc, cur ^ 1, n + 1, v0, tid, bf2, bf3, bf4, local_coords);
        CP_COMMIT();

        const uint32_t* Wbase = smw + FB_W(cur) / 4;
        int bsf = FB_BS(cur) / 4;
        float ev0 = smf[bsf + 448 + r0];
        float ev1 = smf[bsf + 448 + r0 + 8];

        const uint32_t* wA = smw + FB_BUFA / 4;
        const uint32_t* wB = smw + FB_BUFB / 4;

        // ================= L1: bufA -> bufB =================
        {
            float c[4][4];
            #pragma unroll
            for (int a = 0; a < 4; a++)
                #pragma unroll
                for (int b = 0; b < 4; b++) c[a][b] = 0.f;
            gemm16x32_f16(wA, Wbase, mb, cb, lane, c);
            #pragma unroll
            for (int n8 = 0; n8 < 4; n8++) {
                int cc = cb + n8 * 8 + q2;
                float b0 = smf[bsf + cc], b1 = smf[bsf + cc + 1];
                ((__half2*)smc)[FB_BUFB / 4 + r0 * 36 + (cc >> 1)] =
                    __floats2half2_rn(fmaxf(c[n8][0] + b0, 0.f), fmaxf(c[n8][1] + b1, 0.f));
                ((__half2*)smc)[FB_BUFB / 4 + (r0 + 8) * 36 + (cc >> 1)] =
                    __floats2half2_rn(fmaxf(c[n8][2] + b0, 0.f), fmaxf(c[n8][3] + b1, 0.f));
            }
        }
        PAIRB(mb);

        // ================= L2: bufB -> bufA =================
        {
            float c[4][4];
            #pragma unroll
            for (int a = 0; a < 4; a++)
                #pragma unroll
                for (int b = 0; b < 4; b++) c[a][b] = 0.f;
            gemm16x32_f16(wB, Wbase + 4608 / 2, mb, cb, lane, c);
            #pragma unroll
            for (int n8 = 0; n8 < 4; n8++) {
                int cc = cb + n8 * 8 + q2;
                float b0 = smf[bsf + 64 + cc], b1 = smf[bsf + 64 + cc + 1];
                ((__half2*)smc)[FB_BUFA / 4 + r0 * 36 + (cc >> 1)] =
                    __floats2half2_rn(fmaxf(c[n8][0] + b0, 0.f), fmaxf(c[n8][1] + b1, 0.f));
                ((__half2*)smc)[FB_BUFA / 4 + (r0 + 8) * 36 + (cc >> 1)] =
                    __floats2half2_rn(fmaxf(c[n8][2] + b0, 0.f), fmaxf(c[n8][3] + b1, 0.f));
            }
        }
        PAIRB(mb);

        // ================= L3: bufA -> bufB =================
        {
            float c[4][4];
            #pragma unroll
            for (int a = 0; a < 4; a++)
                #pragma unroll
                for (int b = 0; b < 4; b++) c[a][b] = 0.f;
            gemm16x32_f16(wA, Wbase + 9216 / 2, mb, cb, lane, c);
            #pragma unroll
            for (int n8 = 0; n8 < 4; n8++) {
                int cc = cb + n8 * 8 + q2;
                float b0 = smf[bsf + 128 + cc], b1 = smf[bsf + 128 + cc + 1];
                ((__half2*)smc)[FB_BUFB / 4 + r0 * 36 + (cc >> 1)] =
                    __floats2half2_rn(fmaxf(c[n8][0] + b0, 0.f), fmaxf(c[n8][1] + b1, 0.f));
                ((__half2*)smc)[FB_BUFB / 4 + (r0 + 8) * 36 + (cc >> 1)] =
                    __floats2half2_rn(fmaxf(c[n8][2] + b0, 0.f), fmaxf(c[n8][3] + b1, 0.f));
            }
        }
        PAIRB(mb);

        // ================= L4: bufB x W4 (256 cols, 4 rounds) =================
        #pragma unroll
        for (int rnd = 0; rnd < 4; rnd++) {
            float c[4][4];
            #pragma unroll
            for (int a = 0; a < 4; a++)
                #pragma unroll
                for (int b = 0; b < 4; b++) c[a][b] = 0.f;
            int cb4 = rnd * 64 + cb;
            gemm16x32_f16(wB, Wbase + 13824 / 2, mb, cb4, lane, c);
            #pragma unroll
            for (int n8 = 0; n8 < 4; n8++) {
                int cc = cb4 + n8 * 8 + q2;
                float b0 = smf[bsf + 192 + cc], b1 = smf[bsf + 192 + cc + 1];
                int ai = rnd * 16 + n8 * 4;
                acc[ai + 0] += ev0 * fmaxf(c[n8][0] + b0, 0.f);
                acc[ai + 1] += ev0 * fmaxf(c[n8][1] + b1, 0.f);
                acc[ai + 2] += ev1 * fmaxf(c[n8][2] + b0, 0.f);
                acc[ai + 3] += ev1 * fmaxf(c[n8][3] + b1, 0.f);
            }
        }
        cur ^= 1;
        // loop-top __syncthreads() reconverges all pairs before BUFA restage
    }

    // ---- write this group's partial tile ----
    {
        size_t base0 = ((size_t)g * V_PTS + v0 + r0) * 256;
        size_t base1 = ((size_t)g * V_PTS + v0 + r0 + 8) * 256;
        #pragma unroll
        for (int rnd = 0; rnd < 4; rnd++) {
            #pragma unroll
            for (int n8 = 0; n8 < 4; n8++) {
                int cc = rnd * 64 + cb + n8 * 8 + q2;
                int ai = rnd * 16 + n8 * 4;
                *(float2*)&g_fpart[base0 + cc] = make_float2(acc[ai + 0], acc[ai + 1]);
                *(float2*)&g_fpart[base1 + cc] = make_float2(acc[ai + 2], acc[ai + 3]);
            }
        }
    }
}

// =====================================================================
// Kernel D: reduce partials + NeRF head. 8 points per block, 512 thr.
// =====================================================================
__global__ void head_kernel(const float* __restrict__ Wc1, const float* __restrict__ bc1,
                            const float* __restrict__ Wc2, const float* __restrict__ bc2,
                            const float* __restrict__ Wd1, const float* __restrict__ bd1,
                            float* __restrict__ out)
{
    int sub = threadIdx.x >> 6;       // 0..7
    int t   = threadIdx.x & 63;
    int v   = blockIdx.x * 8 + sub;
    __shared__ float f_s[8][256];
    __shared__ float netc_s[8][64];

    {
        float4 s = make_float4(0.f, 0.f, 0.f, 0.f);
        #pragma unroll
        for (int g2 = 0; g2 < NG; g2++) {
            float4 p = *(const float4*)&g_fpart[((size_t)g2 * V_PTS + v) * 256 + t * 4];
            s.x += p.x; s.y += p.y; s.z += p.z; s.w += p.w;
        }
        *(float4*)&f_s[sub][t * 4] = s;
    }
    __syncthreads();

    {
        float a0 = 0.f, a1 = 0.f, a2 = 0.f, a3 = 0.f;
        #pragma unroll 8
        for (int c = 0; c < 256; c += 4) {
            a0 += f_s[sub][c + 0] * Wc1[(c + 0) * 64 + t];
            a1 += f_s[sub][c + 1] * Wc1[(c + 1) * 64 + t];
            a2 += f_s[sub][c + 2] * Wc1[(c + 2) * 64 + t];
            a3 += f_s[sub][c + 3] * Wc1[(c + 3) * 64 + t];
        }
        netc_s[sub][t] = fmaxf(bc1[t] + ((a0 + a1) + (a2 + a3)), 0.f);
    }
    __syncthreads();

    if (t < 3) {
        float r = bc2[t];
        #pragma unroll 8
        for (int j = 0; j < 64; j++) r += netc_s[sub][j] * Wc2[j * 3 + t];
        out[OFF_C + v * 3 + t] = r;
    } else if (t == 3) {
        float r0 = 0.f, r1 = 0.f, r2 = 0.f, r3 = 0.f;
        #pragma unroll 8
        for (int c = 0; c < 256; c += 4) {
            r0 += f_s[sub][c + 0] * Wd1[c + 0];
            r1 += f_s[sub][c + 1] * Wd1[c + 1];
            r2 += f_s[sub][c + 2] * Wd1[c + 2];
            r3 += f_s[sub][c + 3] * Wd1[c + 3];
        }
        out[OFF_D + v] = fmaxf(bd1[0] + ((r0 + r1) + (r2 + r3)), 0.f);
    }
}

// =====================================================================
extern "C" void kernel_launch(void* const* d_in, const int* in_sizes, int n_in,
                              void* d_out, int out_size)
{
    const float* poses = (const float*)d_in[0];
    const float* t_ped = (const float*)d_in[1];
    const float* w     = (const float*)d_in[2];
    const float* wpts  = (const float*)d_in[3];
    const float* nodes = (const float*)d_in[4];
    const float* lc    = (const float*)d_in[5];
    const float *Wec1 = (const float*)d_in[6],  *bec1 = (const float*)d_in[7];
    const float *Wec21= (const float*)d_in[8],  *bec21= (const float*)d_in[9];
    const float *Wec22= (const float*)d_in[10], *bec22= (const float*)d_in[11];
    const float *Wdc1 = (const float*)d_in[12], *bdc1 = (const float*)d_in[13];
    const float *Wdc21= (const float*)d_in[14], *bdc21= (const float*)d_in[15];
    const float *Wdc22= (const float*)d_in[16], *bdc22= (const float*)d_in[17];
    const float *Wf1  = (const float*)d_in[18], *bf1  = (const float*)d_in[19];
    const float *Wf2  = (const float*)d_in[20], *bf2  = (const float*)d_in[21];
    const float *Wf3  = (const float*)d_in[22], *bf3  = (const float*)d_in[23];
    const float *Wf4  = (const float*)d_in[24], *bf4  = (const float*)d_in[25];
    const float *Wc1  = (const float*)d_in[26], *bc1  = (const float*)d_in[27];
    const float *Wc2  = (const float*)d_in[28], *bc2  = (const float*)d_in[29];
    const float *Wd1  = (const float*)d_in[30], *bd1  = (const float*)d_in[31];
    float* out = (float*)d_out;

    setup_kernel<<<N_NODES, 128>>>(poses, t_ped, w,
                                   Wec1, bec1, Wec21, bec21, Wec22, bec22,
                                   Wdc1, bdc1, Wdc21, bdc21, Wdc22, bdc22,
                                   Wf1, bf1, out);
    prep_kernel<<<N_NODES + V_PTS / 256, 256>>>(Wf1, Wf2, Wf3, Wf4, wpts, nodes);

    cudaFuncSetAttribute(field_kernel,
                         cudaFuncAttributeMaxDynamicSharedMemorySize, FB_TOT);
    field_kernel<<<dim3(V_PTS / 128, NG), 512, FB_TOT>>>(lc, bf2, bf3, bf4);

    head_kernel<<<V_PTS / 8, 512>>>(Wc1, bc1, Wc2, bc2, Wd1, bd1, out);
}